// round 14
// baseline (speedup 1.0000x reference)
#include <cuda_runtime.h>

// Problem shapes (fixed by dataset)
#define BB   2
#define CC   64     // channels in
#define OC   64     // channels out
#define KNB  9      // neighbors
#define NMAX 50000

// Scratch: g = relu(W1 @ x + b1), node-major g[b][n][c].
__device__ float g_scratch[(size_t)BB * NMAX * CC];
// Pre-transposed weights (filled by k0 each launch): [c][d] layouts.
__device__ float w1t_g[CC * OC];
__device__ float w2t_g[2 * CC * OC];

// ---- packed f32x2 helpers ---------------------------------------------------
__device__ __forceinline__ unsigned long long pack2(float lo, float hi) {
    unsigned long long r;
    asm("mov.b64 %0, {%1, %2};" : "=l"(r) : "f"(lo), "f"(hi));
    return r;
}
__device__ __forceinline__ void fma2(unsigned long long& acc,
                                     unsigned long long a, unsigned long long b) {
    asm("fma.rn.f32x2 %0, %1, %2, %0;" : "+l"(acc) : "l"(a), "l"(b));
}
__device__ __forceinline__ void unpack2(unsigned long long v, float& lo, float& hi) {
    asm("mov.b64 {%0, %1}, %2;" : "=f"(lo), "=f"(hi) : "l"(v));
}

// ---------------------------------------------------------------------------
// K0: one-off weight transpose into device globals (tiny; scattered stores OK).
// ---------------------------------------------------------------------------
__global__ void k0_transpose(const float* __restrict__ W1,
                             const float* __restrict__ W2)
{
    int t = blockIdx.x * blockDim.x + threadIdx.x;
    for (int e = t; e < CC * OC; e += gridDim.x * blockDim.x) {
        int d = e >> 6, c = e & 63;           // W1[d][c]
        w1t_g[c * OC + d] = W1[e];
    }
    for (int e = t; e < 2 * CC * OC; e += gridDim.x * blockDim.x) {
        int d = e >> 7, ch = e & 127;         // W2[d][ch]
        w2t_g[ch * OC + d] = W2[e];
    }
}

// ---------------------------------------------------------------------------
// K1: per-node 64x64 matvec + bias + relu, f32x2-packed over output channels.
// ---------------------------------------------------------------------------
__global__ void __launch_bounds__(128) k1_node_mlp(
    const float* __restrict__ x,
    const float* __restrict__ b1,
    int N)
{
    __shared__ float w1t[CC * OC];   // [c][d], loaded linearly (conflict-free)
    __shared__ float b1s[OC];

    const int t = threadIdx.x;
    {   // linear float4 copy: coalesced LDG + conflict-free STS.128
        const float4* src = (const float4*)w1t_g;
        float4* dst = (float4*)w1t;
        #pragma unroll
        for (int i = 0; i < (CC * OC / 4) / 128; i++)
            dst[t + i * 128] = src[t + i * 128];
    }
    if (t < OC) b1s[t] = b1[t];
    __syncthreads();

    const int n = blockIdx.x * 128 + t;
    const int b = blockIdx.y;
    if (n >= N) return;

    unsigned long long acc2[OC / 2];
    #pragma unroll
    for (int j = 0; j < OC / 2; j++) acc2[j] = 0ull;

    const float* xp = x + (size_t)b * CC * N + n;
    #pragma unroll 2
    for (int c = 0; c < CC; c++) {
        float xv = xp[(size_t)c * N];                    // coalesced
        unsigned long long xv2 = pack2(xv, xv);
        const ulonglong2* wr = (const ulonglong2*)(w1t + c * OC);
        #pragma unroll
        for (int q = 0; q < OC / 4; q++) {               // 16 x LDS.128 (broadcast)
            ulonglong2 w = wr[q];
            fma2(acc2[2 * q + 0], w.x, xv2);
            fma2(acc2[2 * q + 1], w.y, xv2);
        }
    }

    float4* gp = (float4*)(g_scratch + ((size_t)b * N + n) * CC);
    #pragma unroll
    for (int q = 0; q < OC / 4; q++) {
        float a0, a1, a2, a3;
        unpack2(acc2[2 * q + 0], a0, a1);
        unpack2(acc2[2 * q + 1], a2, a3);
        float4 o;
        o.x = fmaxf(a0 + b1s[4 * q + 0], 0.f);
        o.y = fmaxf(a1 + b1s[4 * q + 1], 0.f);
        o.z = fmaxf(a2 + b1s[4 * q + 2], 0.f);
        o.w = fmaxf(a3 + b1s[4 * q + 3], 0.f);
        gp[q] = o;
    }
}

// ---------------------------------------------------------------------------
// K2: gather-max over 9 neighbors of g, concat with x, 64x128 matvec + relu.
// Block = 256 threads, 32 nodes. cats swizzled; weights staged conflict-free
// from the pre-transposed global; matvec uses packed f32x2 FMA.
// ---------------------------------------------------------------------------
#define TN 32
#define CIDX(ch, nl) ((ch) * TN + (((nl)) ^ ((ch) & 31)))

__global__ void __launch_bounds__(256) k2_gather_mlp(
    const float* __restrict__ x,
    const int*   __restrict__ edge,       // edge_index[0]: [B][N][K] int32
    const float* __restrict__ b2,
    float*       __restrict__ out,
    int N)
{
    __shared__ float cats[2 * CC * TN];   // 128 x 32 floats = 16KB (swizzled)
    __shared__ float w2t[2 * CC * OC];    // [ch][d] = 32KB

    const int t  = threadIdx.x;
    const int b  = blockIdx.y;
    const int n0 = blockIdx.x * TN;

    {   // linear float4 copy of pre-transposed W2: conflict-free
        const float4* src = (const float4*)w2t_g;
        float4* dst = (float4*)w2t;
        #pragma unroll
        for (int i = 0; i < (2 * CC * OC / 4) / 256; i++)
            dst[t + i * 256] = src[t + i * 256];
    }

    // Load x tile into cats channels [0,64)
    #pragma unroll
    for (int i = 0; i < (CC * TN) / 256; i++) {
        int e  = t + i * 256;
        int c  = e >> 5, nl = e & 31;
        int n  = n0 + nl;
        cats[CIDX(c, nl)] = (n < N) ? x[((size_t)b * CC + c) * N + n] : 0.f;
    }

    // Gather-max: warp w handles 4 nodes; lane l owns channels l and l+32.
    {
        const int w = t >> 5, l = t & 31;
        #pragma unroll
        for (int j = 0; j < 4; j++) {
            int nl = w * 4 + j;
            int n  = n0 + nl;
            float m0 = 0.f, m1 = 0.f;     // relu output >= 0, so 0 acts as -inf
            if (n < N) {
                const int* ep = edge + ((size_t)b * N + n) * KNB;
                #pragma unroll
                for (int k = 0; k < KNB; k++) {
                    int m = ep[k];                     // broadcast load in warp
                    m = min(max(m, 0), N - 1);         // defensive clamp
                    const float* gp = g_scratch + ((size_t)b * N + m) * CC;
                    m0 = fmaxf(m0, gp[l]);             // coalesced 128B
                    m1 = fmaxf(m1, gp[32 + l]);        // coalesced 128B
                }
            }
            cats[CIDX(CC + l,      nl)] = m0;
            cats[CIDX(CC + 32 + l, nl)] = m1;
        }
    }
    __syncthreads();

    // Matvec: thread = (node nl, 8 output channels d0..d0+7), f32x2-packed.
    const int nl = t & 31;
    const int d0 = (t >> 5) * 8;
    const int n  = n0 + nl;

    unsigned long long acc2[4];
    #pragma unroll
    for (int j = 0; j < 4; j++) acc2[j] = 0ull;

    #pragma unroll 4
    for (int ch = 0; ch < 2 * CC; ch++) {
        float v = cats[CIDX(ch, nl)];
        unsigned long long v2 = pack2(v, v);
        const ulonglong2* wp = (const ulonglong2*)(w2t + ch * OC + d0);
        ulonglong2 wa = wp[0], wb = wp[1];             // 2 x LDS.128 (broadcast)
        fma2(acc2[0], wa.x, v2);
        fma2(acc2[1], wa.y, v2);
        fma2(acc2[2], wb.x, v2);
        fma2(acc2[3], wb.y, v2);
    }

    if (n < N) {
        float r[8];
        unpack2(acc2[0], r[0], r[1]);
        unpack2(acc2[1], r[2], r[3]);
        unpack2(acc2[2], r[4], r[5]);
        unpack2(acc2[3], r[6], r[7]);
        #pragma unroll
        for (int j = 0; j < 8; j++) {
            float bias = __ldg(&b2[d0 + j]);
            out[((size_t)b * OC + d0 + j) * N + n] = fmaxf(r[j] + bias, 0.f);
        }
    }
}

// ---------------------------------------------------------------------------
extern "C" void kernel_launch(void* const* d_in, const int* in_sizes, int n_in,
                              void* d_out, int out_size)
{
    const float* x    = (const float*)d_in[0];      // [B,C,N,1] f32
    const int*   edge = (const int*)d_in[1];        // [2,B,N,K] int32 (use [0])
    const float* W1   = (const float*)d_in[2];      // [C,C]
    const float* b1   = (const float*)d_in[3];      // [C]
    const float* W2   = (const float*)d_in[4];      // [OC,2C]
    const float* b2   = (const float*)d_in[5];      // [OC]
    float*       out  = (float*)d_out;              // [B,OC,N,1]

    const int N = in_sizes[0] / (BB * CC);

    k0_transpose<<<8, 256>>>(W1, W2);

    dim3 g1((N + 127) / 128, BB);
    k1_node_mlp<<<g1, 128>>>(x, b1, N);

    dim3 g2((N + TN - 1) / TN, BB);
    k2_gather_mlp<<<g2, 256>>>(x, edge, b2, out, N);
}

// round 15
// speedup vs baseline: 1.0506x; 1.0506x over previous
#include <cuda_runtime.h>

// Problem shapes (fixed by dataset)
#define BB   2
#define CC   64     // channels in
#define OC   64     // channels out
#define KNB  9      // neighbors
#define NMAX 50000

// Scratch: g = relu(W1 @ x + b1), node-major g[b][n][c].
__device__ float g_scratch[(size_t)BB * NMAX * CC];
// Pre-transposed weights (filled by k0 each launch): [c][d] layouts.
__device__ float w1t_g[CC * OC];
__device__ float w2t_g[2 * CC * OC];

// ---- packed f32x2 helpers ---------------------------------------------------
__device__ __forceinline__ unsigned long long pack2(float lo, float hi) {
    unsigned long long r;
    asm("mov.b64 %0, {%1, %2};" : "=l"(r) : "f"(lo), "f"(hi));
    return r;
}
__device__ __forceinline__ void fma2(unsigned long long& acc,
                                     unsigned long long a, unsigned long long b) {
    asm("fma.rn.f32x2 %0, %1, %2, %0;" : "+l"(acc) : "l"(a), "l"(b));
}
__device__ __forceinline__ void unpack2(unsigned long long v, float& lo, float& hi) {
    asm("mov.b64 {%0, %1}, %2;" : "=f"(lo), "=f"(hi) : "l"(v));
}

// ---------------------------------------------------------------------------
// K0: one-off weight transpose into device globals (tiny; scattered stores OK).
// ---------------------------------------------------------------------------
__global__ void k0_transpose(const float* __restrict__ W1,
                             const float* __restrict__ W2)
{
    int t = blockIdx.x * blockDim.x + threadIdx.x;
    for (int e = t; e < CC * OC; e += gridDim.x * blockDim.x) {
        int d = e >> 6, c = e & 63;           // W1[d][c]
        w1t_g[c * OC + d] = W1[e];
    }
    for (int e = t; e < 2 * CC * OC; e += gridDim.x * blockDim.x) {
        int d = e >> 7, ch = e & 127;         // W2[d][ch]
        w2t_g[ch * OC + d] = W2[e];
    }
}

// ---------------------------------------------------------------------------
// K1: per-node 64x64 matvec + bias + relu, f32x2-packed over output channels.
// ---------------------------------------------------------------------------
__global__ void __launch_bounds__(128) k1_node_mlp(
    const float* __restrict__ x,
    const float* __restrict__ b1,
    int N)
{
    __shared__ float w1t[CC * OC];   // [c][d], loaded linearly (conflict-free)
    __shared__ float b1s[OC];

    const int t = threadIdx.x;
    {   // linear float4 copy: coalesced LDG + conflict-free STS.128
        const float4* src = (const float4*)w1t_g;
        float4* dst = (float4*)w1t;
        #pragma unroll
        for (int i = 0; i < (CC * OC / 4) / 128; i++)
            dst[t + i * 128] = src[t + i * 128];
    }
    if (t < OC) b1s[t] = b1[t];
    __syncthreads();

    const int n = blockIdx.x * 128 + t;
    const int b = blockIdx.y;
    if (n >= N) return;

    unsigned long long acc2[OC / 2];
    #pragma unroll
    for (int j = 0; j < OC / 2; j++) acc2[j] = 0ull;

    const float* xp = x + (size_t)b * CC * N + n;
    #pragma unroll 2
    for (int c = 0; c < CC; c++) {
        float xv = xp[(size_t)c * N];                    // coalesced
        unsigned long long xv2 = pack2(xv, xv);
        const ulonglong2* wr = (const ulonglong2*)(w1t + c * OC);
        #pragma unroll
        for (int q = 0; q < OC / 4; q++) {               // 16 x LDS.128 (broadcast)
            ulonglong2 w = wr[q];
            fma2(acc2[2 * q + 0], w.x, xv2);
            fma2(acc2[2 * q + 1], w.y, xv2);
        }
    }

    float4* gp = (float4*)(g_scratch + ((size_t)b * N + n) * CC);
    #pragma unroll
    for (int q = 0; q < OC / 4; q++) {
        float a0, a1, a2, a3;
        unpack2(acc2[2 * q + 0], a0, a1);
        unpack2(acc2[2 * q + 1], a2, a3);
        float4 o;
        o.x = fmaxf(a0 + b1s[4 * q + 0], 0.f);
        o.y = fmaxf(a1 + b1s[4 * q + 1], 0.f);
        o.z = fmaxf(a2 + b1s[4 * q + 2], 0.f);
        o.w = fmaxf(a3 + b1s[4 * q + 3], 0.f);
        gp[q] = o;
    }
}

// ---------------------------------------------------------------------------
// K2: gather-max over 9 neighbors of g, concat with x, 64x128 matvec + relu.
// Block = 256 threads, 32 nodes. cats swizzled; weights staged conflict-free
// from the pre-transposed global; matvec uses packed f32x2 FMA.
// ---------------------------------------------------------------------------
#define TN 32
#define CIDX(ch, nl) ((ch) * TN + (((nl)) ^ ((ch) & 31)))

__global__ void __launch_bounds__(256) k2_gather_mlp(
    const float* __restrict__ x,
    const int*   __restrict__ edge,       // edge_index[0]: [B][N][K] int32
    const float* __restrict__ b2,
    float*       __restrict__ out,
    int N)
{
    __shared__ float cats[2 * CC * TN];   // 128 x 32 floats = 16KB (swizzled)
    __shared__ float w2t[2 * CC * OC];    // [ch][d] = 32KB

    const int t  = threadIdx.x;
    const int b  = blockIdx.y;
    const int n0 = blockIdx.x * TN;

    {   // linear float4 copy of pre-transposed W2: conflict-free
        const float4* src = (const float4*)w2t_g;
        float4* dst = (float4*)w2t;
        #pragma unroll
        for (int i = 0; i < (2 * CC * OC / 4) / 256; i++)
            dst[t + i * 256] = src[t + i * 256];
    }

    // Load x tile into cats channels [0,64)
    #pragma unroll
    for (int i = 0; i < (CC * TN) / 256; i++) {
        int e  = t + i * 256;
        int c  = e >> 5, nl = e & 31;
        int n  = n0 + nl;
        cats[CIDX(c, nl)] = (n < N) ? x[((size_t)b * CC + c) * N + n] : 0.f;
    }

    // Gather-max: warp w handles 4 nodes; lane l owns channels l and l+32.
    {
        const int w = t >> 5, l = t & 31;
        #pragma unroll
        for (int j = 0; j < 4; j++) {
            int nl = w * 4 + j;
            int n  = n0 + nl;
            float m0 = 0.f, m1 = 0.f;     // relu output >= 0, so 0 acts as -inf
            if (n < N) {
                const int* ep = edge + ((size_t)b * N + n) * KNB;
                #pragma unroll
                for (int k = 0; k < KNB; k++) {
                    int m = ep[k];                     // broadcast load in warp
                    m = min(max(m, 0), N - 1);         // defensive clamp
                    const float* gp = g_scratch + ((size_t)b * N + m) * CC;
                    m0 = fmaxf(m0, gp[l]);             // coalesced 128B
                    m1 = fmaxf(m1, gp[32 + l]);        // coalesced 128B
                }
            }
            cats[CIDX(CC + l,      nl)] = m0;
            cats[CIDX(CC + 32 + l, nl)] = m1;
        }
    }
    __syncthreads();

    // Matvec: thread = (node nl, 8 output channels d0..d0+7), f32x2-packed.
    const int nl = t & 31;
    const int d0 = (t >> 5) * 8;
    const int n  = n0 + nl;

    unsigned long long acc2[4];
    #pragma unroll
    for (int j = 0; j < 4; j++) acc2[j] = 0ull;

    #pragma unroll 4
    for (int ch = 0; ch < 2 * CC; ch++) {
        float v = cats[CIDX(ch, nl)];
        unsigned long long v2 = pack2(v, v);
        const ulonglong2* wp = (const ulonglong2*)(w2t + ch * OC + d0);
        ulonglong2 wa = wp[0], wb = wp[1];             // 2 x LDS.128 (broadcast)
        fma2(acc2[0], wa.x, v2);
        fma2(acc2[1], wa.y, v2);
        fma2(acc2[2], wb.x, v2);
        fma2(acc2[3], wb.y, v2);
    }

    if (n < N) {
        float r[8];
        unpack2(acc2[0], r[0], r[1]);
        unpack2(acc2[1], r[2], r[3]);
        unpack2(acc2[2], r[4], r[5]);
        unpack2(acc2[3], r[6], r[7]);
        #pragma unroll
        for (int j = 0; j < 8; j++) {
            float bias = __ldg(&b2[d0 + j]);
            out[((size_t)b * OC + d0 + j) * N + n] = fmaxf(r[j] + bias, 0.f);
        }
    }
}

// ---------------------------------------------------------------------------
extern "C" void kernel_launch(void* const* d_in, const int* in_sizes, int n_in,
                              void* d_out, int out_size)
{
    const float* x    = (const float*)d_in[0];      // [B,C,N,1] f32
    const int*   edge = (const int*)d_in[1];        // [2,B,N,K] int32 (use [0])
    const float* W1   = (const float*)d_in[2];      // [C,C]
    const float* b1   = (const float*)d_in[3];      // [C]
    const float* W2   = (const float*)d_in[4];      // [OC,2C]
    const float* b2   = (const float*)d_in[5];      // [OC]
    float*       out  = (float*)d_out;              // [B,OC,N,1]

    const int N = in_sizes[0] / (BB * CC);

    k0_transpose<<<8, 256>>>(W1, W2);

    dim3 g1((N + 127) / 128, BB);
    k1_node_mlp<<<g1, 128>>>(x, b1, N);

    dim3 g2((N + TN - 1) / TN, BB);
    k2_gather_mlp<<<g2, 256>>>(x, edge, b2, out, N);
}